// round 14
// baseline (speedup 1.0000x reference)
#include <cuda_runtime.h>
#include <math.h>

#define BB 64
#define HH 14
#define WW 14
#define CC 32
#define OO 10
#define NN (HH*WW*CC)          /* 6272 */
#define HALF_S 98
#define NBLK 128               /* persistent blocks */
#define G 8                    /* points per staged group */
#define NGRP 13                /* 12 groups of 8 + one of 2 */
#define TPB 352                /* 32 x 11 */
#define EPSV 1e-9f
#define LOG2E 1.4426950408889634f
#define LN2PI 1.8378770664093453f

/* double-buffered cross-block partials: [parity][half][b][o][33] */
__device__ float g_part[2][2*BB*OO*33];
/* per-block moment stats for factored IT0: [blk][stat][c] */
__device__ float g_mst[NBLK][72*CC];
__device__ unsigned int g_ctr;
__device__ unsigned int g_epoch;

typedef unsigned long long u64;
__device__ __forceinline__ u64 pk2(float lo, float hi){ u64 r; asm("mov.b64 %0,{%1,%2};" :"=l"(r):"f"(lo),"f"(hi)); return r; }
__device__ __forceinline__ void upk2(u64 a, float& lo, float& hi){ asm("mov.b64 {%0,%1},%2;":"=f"(lo),"=f"(hi):"l"(a)); }
__device__ __forceinline__ u64 fma2(u64 a,u64 b,u64 c){ u64 r; asm("fma.rn.f32x2 %0,%1,%2,%3;":"=l"(r):"l"(a),"l"(b),"l"(c)); return r; }
__device__ __forceinline__ u64 add2(u64 a,u64 b){ u64 r; asm("add.rn.f32x2 %0,%1,%2;":"=l"(r):"l"(a),"l"(b)); return r; }
__device__ __forceinline__ u64 mul2(u64 a,u64 b){ u64 r; asm("mul.rn.f32x2 %0,%1,%2;":"=l"(r):"l"(a),"l"(b)); return r; }
__device__ __forceinline__ float ex2f(float x){ float r; asm("ex2.approx.f32 %0,%1;":"=f"(r):"f"(x)); return r; }
__device__ __forceinline__ float rcpf(float x){ float r; asm("rcp.approx.f32 %0,%1;":"=f"(r):"f"(x)); return r; }

struct Shm {
    float  act [HALF_S*CC];      /* 12544 B */
    float  sbuf[G*CC*18];        /* 18432 B : pair-swizzled pose; aliased as
                                    reduction scratch [11][10][33] (14520 B) */
    u64    offs[HALF_S];
    u64    A2pk[OO*8];           /* packed -0.5/var*log2e */
    u64    Mpk [OO*8];           /* packed -mu */
    float  Mu  [OO*16];
    float  C0  [OO];
    unsigned e0;
};

__device__ __forceinline__ void grid_barrier(unsigned target_epoch){
    __threadfence();
    __syncthreads();
    if (threadIdx.x == 0 && threadIdx.y == 0){
        unsigned a = atomicAdd(&g_ctr, 1u);
        if (a == NBLK-1u){
            atomicExch(&g_ctr, 0u);
            __threadfence();
            atomicAdd(&g_epoch, 1u);
        } else {
            while ((int)(*(volatile unsigned*)&g_epoch) - (int)target_epoch < 0) { }
        }
    }
    __syncthreads();
}

__device__ __forceinline__ void ldg_rows(const float4* pb4, int g, int t,
                                         float4& p0, float4& p1, float4& p2, float4& p3){
    const float4* s = pb4 + ((size_t)g*G*CC + t)*4;
    p0 = s[0]; p1 = s[1]; p2 = s[2]; p3 = s[3];
}
__device__ __forceinline__ void sts_row(float* slotbuf, int t,
                                        const float4& p0, const float4& p1,
                                        const float4& p2, const float4& p3){
    float2* sb2 = (float2*)&slotbuf[t*18];
    sb2[0] = make_float2(p0.x, p1.x);
    sb2[1] = make_float2(p0.y, p1.y);
    sb2[2] = make_float2(p0.z, p1.z);
    sb2[3] = make_float2(p0.w, p1.w);
    sb2[4] = make_float2(p2.x, p3.x);
    sb2[5] = make_float2(p2.y, p3.y);
    sb2[6] = make_float2(p2.z, p3.z);
    sb2[7] = make_float2(p2.w, p3.w);
}

/* ------------- soft pass (IT>0): warp-transposed softmax mapping.
   lane = grp*10 + o (grp = c-slot within warp, o = output capsule);
   warp w handles c = {3w, 3w+1, 3w+2}. Softmax over o is intra-warp
   shuffles over 10 adjacent lanes — no block syncs in the point loop. ---- */
__device__ __forceinline__ void stats_pass_soft(
    const float* __restrict__ pose_blk, Shm* sh,
    const u64 wpk[4][4],
    int tx, int ty, int os, int base, int active, int cs,
    int r1s, int r2s, int r4s, int r8s,
    float* gp_base)
{
    u64 A2[2][4], nMU[2][4];
    const float C0 = sh->C0[os];
#pragma unroll
    for (int p = 0; p < 2; p++)
#pragma unroll
    for (int k = 0; k < 4; k++){
        A2[p][k]  = sh->A2pk[os*8 + p*4 + k];
        nMU[p][k] = sh->Mpk [os*8 + p*4 + k];
    }

    u64 S1[2][4], S2[2][4]; float S0 = 0.f;
#pragma unroll
    for (int p = 0; p < 2; p++)
#pragma unroll
    for (int k = 0; k < 4; k++){ S1[p][k] = 0ull; S2[p][k] = 0ull; }

    const int t = ty*32 + tx;
    const float4* pb4 = (const float4*)pose_blk;

    float4 pr0, pr1, pr2, pr3;
    if (t < G*CC) ldg_rows(pb4, 0, t, pr0, pr1, pr2, pr3);

    for (int g = 0; g < NGRP; g++){
        const int pts = (g == NGRP-1) ? (HALF_S - (NGRP-1)*G) : G;   /* 8 or 2 */
        if (t < pts*CC) sts_row(sh->sbuf, t, pr0, pr1, pr2, pr3);
        __syncthreads();
        if (g < NGRP-1){
            const int npts = (g == NGRP-2) ? (HALF_S - (NGRP-1)*G) : G;
            if (t < npts*CC) ldg_rows(pb4, g+1, t, pr0, pr1, pr2, pr3);
        }

#pragma unroll 2
        for (int lp = 0; lp < pts; lp++){
            const u64* q = (const u64*)(sh->sbuf) + ((size_t)lp*CC + cs)*9;
            const u64 j0a = q[0], j1a = q[1], j2a = q[2], j3a = q[3];
            const u64 j0b = q[4], j1b = q[5], j2b = q[6], j3b = q[7];

            u64 u[2][4];
#pragma unroll
            for (int k = 0; k < 4; k++){
                u64 a0 = fma2(j0a, wpk[0][k], nMU[0][k]);
                u64 a1 = fma2(j0b, wpk[0][k], nMU[1][k]);
                a0 = fma2(j1a, wpk[1][k], a0);
                a1 = fma2(j1b, wpk[1][k], a1);
                a0 = fma2(j2a, wpk[2][k], a0);
                a1 = fma2(j2b, wpk[2][k], a1);
                a0 = fma2(j3a, wpk[3][k], a0);
                a1 = fma2(j3b, wpk[3][k], a1);
                u[0][k] = a0; u[1][k] = a1;
            }
            u[0][3] = add2(u[0][3], sh->offs[g*G + lp]);

            u64 q2, l2;
            q2 = mul2(u[0][0], u[0][0]); l2 = mul2(q2, A2[0][0]);
            q2 = mul2(u[0][1], u[0][1]); l2 = fma2(q2, A2[0][1], l2);
            q2 = mul2(u[0][2], u[0][2]); l2 = fma2(q2, A2[0][2], l2);
            q2 = mul2(u[0][3], u[0][3]); l2 = fma2(q2, A2[0][3], l2);
            q2 = mul2(u[1][0], u[1][0]); l2 = fma2(q2, A2[1][0], l2);
            q2 = mul2(u[1][1], u[1][1]); l2 = fma2(q2, A2[1][1], l2);
            q2 = mul2(u[1][2], u[1][2]); l2 = fma2(q2, A2[1][2], l2);
            q2 = mul2(u[1][3], u[1][3]); l2 = fma2(q2, A2[1][3], l2);
            float x, y; upk2(l2, x, y);
            const float lg = C0 + (x + y);

            /* warp-group softmax over the 10 o-lanes of this c */
            float m = lg, tt;
            tt = __shfl_sync(0xffffffffu, m, r1s); m = fmaxf(m, tt);
            tt = __shfl_sync(0xffffffffu, m, r2s); m = fmaxf(m, tt);
            tt = __shfl_sync(0xffffffffu, m, r4s); m = fmaxf(m, tt);
            tt = __shfl_sync(0xffffffffu, m, r8s); m = fmaxf(m, tt);
            const float e = ex2f(lg - m);
            float s = e;
            tt = __shfl_sync(0xffffffffu, s, tx+5); if (os < 5) s += tt;
            tt = __shfl_sync(0xffffffffu, s, tx+1); if (((os & 1) == 0) && (os < 4)) s += tt;
            tt = __shfl_sync(0xffffffffu, s, tx+2); if (os == 0) s += tt;
            tt = __shfl_sync(0xffffffffu, s, tx+4); if (os == 0) s += tt;
            s = __shfl_sync(0xffffffffu, s, base);
            const float rr = e * rcpf(s);

            const float av = active ? sh->act[(g*G + lp)*CC + cs] : 0.f;
            const float rp = rr * av;
            S0 += rp;
            const u64 rk = pk2(rp, rp);
#pragma unroll
            for (int p = 0; p < 2; p++)
#pragma unroll
            for (int k = 0; k < 4; k++){
                const u64 ru = mul2(rk, u[p][k]);
                S1[p][k] = add2(S1[p][k], ru);
                S2[p][k] = fma2(ru, u[p][k], S2[p][k]);
            }
        }
        __syncthreads();   /* sbuf reads done before next group's STS */
    }

    /* reduction: unpack, fold the 3 c-groups within each warp, then
       cross-warp sum through scratch aliased over sbuf */
    float f[33];
#pragma unroll
    for (int p = 0; p < 2; p++)
#pragma unroll
    for (int k = 0; k < 4; k++){
        upk2(S1[p][k], f[p*8+k],    f[p*8+4+k]);
        upk2(S2[p][k], f[16+p*8+k], f[16+p*8+4+k]);
    }
    f[32] = S0;
#pragma unroll
    for (int i = 0; i < 33; i++){
        const float t1 = __shfl_sync(0xffffffffu, f[i], tx+10);
        const float t2 = __shfl_sync(0xffffffffu, f[i], tx+20);
        f[i] += t1 + t2;    /* valid on lanes 0-9 */
    }
    float* scratch = sh->sbuf;   /* [11][10][33] */
    if (tx < 10){
#pragma unroll
        for (int i = 0; i < 33; i++) scratch[((size_t)ty*10 + tx)*33 + i] = f[i];
    }
    __syncthreads();
    if (t < 330){
        const int o2 = t / 33, i2 = t - o2*33;
        float s = 0.f;
#pragma unroll
        for (int w = 0; w < 11; w++) s += scratch[((size_t)w*10 + o2)*33 + i2];
        gp_base[o2*33 + i2] = s;
    }
    __syncthreads();
}

/* ---------------- factored IT0 (old mapping c=tx, o=ty), unchanged math ---- */
__device__ __forceinline__ void stats_zero_fact(
    const float* __restrict__ pose_blk, Shm* sh,
    const float* __restrict__ wmat, int c, int o, float* gp, int blk)
{
    float acc[10];
#pragma unroll
    for (int i = 0; i < 10; i++) acc[i] = 0.f;

    const int t = o*32 + c;
    const float4* pb4 = (const float4*)pose_blk;

    float4 pr0, pr1, pr2, pr3;
    if (t < G*CC) ldg_rows(pb4, 0, t, pr0, pr1, pr2, pr3);

    for (int g = 0; g < NGRP; g++){
        const int pts = (g == NGRP-1) ? (HALF_S - (NGRP-1)*G) : G;
        if (t < pts*CC) sts_row(sh->sbuf, t, pr0, pr1, pr2, pr3);
        __syncthreads();
        if (g < NGRP-1){
            const int npts = (g == NGRP-2) ? (HALF_S - (NGRP-1)*G) : G;
            if (t < npts*CC) ldg_rows(pb4, g+1, t, pr0, pr1, pr2, pr3);
        }

        for (int lp = 0; lp < pts; lp++){
            const float a = sh->act[(g*G + lp)*CC + c];
            const float2* q2 = (const float2*)(sh->sbuf) + ((size_t)lp*CC + c)*9;
            if (o < 4){
                const int bs = (o >> 1) << 2;
                const float2 a0 = q2[bs], a1 = q2[bs+1], a2 = q2[bs+2], a3 = q2[bs+3];
                const float p0 = (o & 1) ? a0.y : a0.x;
                const float p1 = (o & 1) ? a1.y : a1.x;
                const float p2 = (o & 1) ? a2.y : a2.x;
                const float p3 = (o & 1) ? a3.y : a3.x;
                const float t0 = a*p0, t1 = a*p1, t2 = a*p2, t3 = a*p3;
                acc[0]=fmaf(t0,p0,acc[0]); acc[1]=fmaf(t0,p1,acc[1]);
                acc[2]=fmaf(t0,p2,acc[2]); acc[3]=fmaf(t0,p3,acc[3]);
                acc[4]=fmaf(t1,p1,acc[4]); acc[5]=fmaf(t1,p2,acc[5]);
                acc[6]=fmaf(t1,p3,acc[6]); acc[7]=fmaf(t2,p2,acc[7]);
                acc[8]=fmaf(t2,p3,acc[8]); acc[9]=fmaf(t3,p3,acc[9]);
            } else if (o < 6){
                const int bs = (o == 5) ? 4 : 0;
                const float2 a0 = q2[bs], a1 = q2[bs+1], a2 = q2[bs+2], a3 = q2[bs+3];
                acc[0]=fmaf(a,a0.x,acc[0]); acc[1]=fmaf(a,a1.x,acc[1]);
                acc[2]=fmaf(a,a2.x,acc[2]); acc[3]=fmaf(a,a3.x,acc[3]);
                acc[4]=fmaf(a,a0.y,acc[4]); acc[5]=fmaf(a,a1.y,acc[5]);
                acc[6]=fmaf(a,a2.y,acc[6]); acc[7]=fmaf(a,a3.y,acc[7]);
            } else if (o == 6){
                float ow, oh; upk2(sh->offs[g*G+lp], ow, oh);
                acc[0] += a;
                acc[1] = fmaf(a, ow, acc[1]);
                acc[2] = fmaf(a, oh, acc[2]);
                acc[3] = fmaf(a*ow, ow, acc[3]);
                acc[4] = fmaf(a*oh, oh, acc[4]);
            } else if (o == 7){
                float ow, oh; upk2(sh->offs[g*G+lp], ow, oh);
                const float aw = a*ow;
                const float2 a0 = q2[0], a1 = q2[1], a2 = q2[2], a3 = q2[3];
                acc[0]=fmaf(aw,a0.x,acc[0]); acc[1]=fmaf(aw,a1.x,acc[1]);
                acc[2]=fmaf(aw,a2.x,acc[2]); acc[3]=fmaf(aw,a3.x,acc[3]);
            } else if (o == 8){
                float ow, oh; upk2(sh->offs[g*G+lp], ow, oh);
                const float ah = a*oh;
                const float2 a0 = q2[0], a1 = q2[1], a2 = q2[2], a3 = q2[3];
                acc[0]=fmaf(ah,a0.y,acc[0]); acc[1]=fmaf(ah,a1.y,acc[1]);
                acc[2]=fmaf(ah,a2.y,acc[2]); acc[3]=fmaf(ah,a3.y,acc[3]);
            }
        }
        __syncthreads();
    }

    float* mst = g_mst[blk];
    if (o < 4){
#pragma unroll
        for (int s = 0; s < 10; s++) mst[(16 + o*10 + s)*CC + c] = acc[s];
    } else if (o == 4){
#pragma unroll
        for (int s = 0; s < 8; s++) mst[s*CC + c] = acc[s];
    } else if (o == 5){
#pragma unroll
        for (int s = 0; s < 8; s++) mst[(8+s)*CC + c] = acc[s];
    } else if (o == 6){
#pragma unroll
        for (int s = 0; s < 5; s++) mst[(56+s)*CC + c] = acc[s];
    } else if (o == 7){
#pragma unroll
        for (int s = 0; s < 4; s++) mst[(61+s)*CC + c] = acc[s];
    } else if (o == 8){
#pragma unroll
        for (int s = 0; s < 4; s++) mst[(65+s)*CC + c] = acc[s];
    }
    __syncthreads();

    if (o < 10){
        float wv[4][4];
#pragma unroll
        for (int j = 0; j < 4; j++)
#pragma unroll
        for (int k = 0; k < 4; k++)
            wv[j][k] = wmat[((size_t)(c*OO + o))*16 + j*4 + k];

        float Mp[16];
#pragma unroll
        for (int s = 0; s < 16; s++) Mp[s] = mst[s*CC + c];
        float Mpp[40];
#pragma unroll
        for (int s = 0; s < 40; s++) Mpp[s] = mst[(16+s)*CC + c];
        const float M0  = mst[56*CC + c];
        const float Mw  = mst[57*CC + c];
        const float Mh  = mst[58*CC + c];
        const float Mw2 = mst[59*CC + c];
        const float Mh2 = mst[60*CC + c];
        float Mwp[4], Mhp[4];
#pragma unroll
        for (int s = 0; s < 4; s++){ Mwp[s] = mst[(61+s)*CC + c]; Mhp[s] = mst[(65+s)*CC + c]; }

        float f[33];
#pragma unroll
        for (int i = 0; i < 4; i++)
#pragma unroll
        for (int k = 0; k < 4; k++){
            float s = Mp[i*4+0]*wv[0][k];
            s = fmaf(Mp[i*4+1], wv[1][k], s);
            s = fmaf(Mp[i*4+2], wv[2][k], s);
            s = fmaf(Mp[i*4+3], wv[3][k], s);
            f[i*4+k] = s;
        }
        f[3] += Mw; f[7] += Mh;
#pragma unroll
        for (int k = 0; k < 4; k++){
            float pr[10];
            pr[0] = wv[0][k]*wv[0][k];
            pr[1] = 2.f*wv[0][k]*wv[1][k];
            pr[2] = 2.f*wv[0][k]*wv[2][k];
            pr[3] = 2.f*wv[0][k]*wv[3][k];
            pr[4] = wv[1][k]*wv[1][k];
            pr[5] = 2.f*wv[1][k]*wv[2][k];
            pr[6] = 2.f*wv[1][k]*wv[3][k];
            pr[7] = wv[2][k]*wv[2][k];
            pr[8] = 2.f*wv[2][k]*wv[3][k];
            pr[9] = wv[3][k]*wv[3][k];
#pragma unroll
            for (int i = 0; i < 4; i++){
                const float* mp = Mpp + i*10;
                float s = mp[0]*pr[0];
#pragma unroll
                for (int tt = 1; tt < 10; tt++) s = fmaf(mp[tt], pr[tt], s);
                f[16 + i*4 + k] = s;
            }
        }
        {
            float cw = Mwp[0]*wv[0][3];
            cw = fmaf(Mwp[1], wv[1][3], cw);
            cw = fmaf(Mwp[2], wv[2][3], cw);
            cw = fmaf(Mwp[3], wv[3][3], cw);
            f[16+3] += 2.f*cw + Mw2;
            float ch = Mhp[0]*wv[0][3];
            ch = fmaf(Mhp[1], wv[1][3], ch);
            ch = fmaf(Mhp[2], wv[2][3], ch);
            ch = fmaf(Mhp[3], wv[3][3], ch);
            f[16+7] += 2.f*ch + Mh2;
        }
        f[32] = 0.1f*M0;
#pragma unroll
        for (int s = 0; s < 32; s++) f[s] *= 0.1f;

#pragma unroll
        for (int off = 16; off > 0; off >>= 1){
#pragma unroll
            for (int i = 0; i < 33; i++)
                f[i] += __shfl_down_sync(0xffffffffu, f[i], off);
        }
        if (c == 0){
#pragma unroll
            for (int i = 0; i < 33; i++) gp[i] = f[i];
        }
    }
}

__device__ __forceinline__ void block_finalize(
    int it, int b, int tid, Shm* sh,
    const float* __restrict__ beta_a, const float* __restrict__ beta_u,
    float* __restrict__ out)
{
    if (tid < 160){
        const int o = tid >> 4, d = tid & 15;
        const float* buf = g_part[it & 1];
        const float* gp0 = &buf[((0*BB + b)*OO + o)*33];
        const float* gp1 = &buf[((1*BB + b)*OO + o)*33];
        const float T1 = __ldcg(gp0 + d)      + __ldcg(gp1 + d);
        const float T2 = __ldcg(gp0 + 16 + d) + __ldcg(gp1 + 16 + d);
        const float S0 = __ldcg(gp0 + 32)     + __ldcg(gp1 + 32);
        const float mu_prev = (it == 0) ? 0.f : sh->Mu[o*16 + d];

        const double S0d = (double)S0;
        const double rsd = S0d + (double)EPSV;
        const double S1d = (double)T1 + (double)mu_prev * S0d;
        const double mud = S1d / rsd;
        const double e   = mud - (double)mu_prev;
        double varnum = (double)T2 - 2.0*e*(double)T1 + e*e*S0d;
        if (varnum < 0.0) varnum = 0.0;
        const double vard = varnum / rsd + (double)EPSV;

        const float mu   = (float)mud;
        const float var  = (float)vard;
        const float lvar = logf(var);
        const float iv   = 1.0f/var;
        const float rs   = (float)rsd;

        float r1 = lvar;
#pragma unroll
        for (int m = 8; m > 0; m >>= 1)
            r1 += __shfl_xor_sync(0xffffffffu, r1, m);

        const float cost     = rs * (16.0f*beta_u[o] + 0.5f*r1);
        const float inv_temp = 1.0f + (float)it;
        const float z        = inv_temp * (beta_a[o] - cost);
        const float actv     = 1.0f / (1.0f + expf(-z));

        if (it < 2){
            const int p = d >> 3, hi = (d >> 2) & 1, k = d & 3;
            ((float*)&sh->A2pk[o*8 + p*4 + k])[hi] = -0.5f*iv*LOG2E;
            ((float*)&sh->Mpk [o*8 + p*4 + k])[hi] = -mu;
            sh->Mu[o*16 + d] = mu;
            if (d == 0)
                sh->C0[o] = (logf(actv + EPSV) - 0.5f*(16.0f*LN2PI + r1)) * LOG2E;
        } else {
            out[(b*OO + o)*16 + d] = mu;
            if (d == 0) out[BB*OO*16 + b*OO + o] = actv;
        }
    }
    __syncthreads();
}

__global__ __launch_bounds__(TPB)
void fccaps_kernel(const float* __restrict__ pose,
                   const float* __restrict__ act,
                   const float* __restrict__ wmat,
                   const float* __restrict__ beta_a,
                   const float* __restrict__ beta_u,
                   float* __restrict__ out)
{
    __shared__ Shm sh;

    const int tx  = threadIdx.x;
    const int ty  = threadIdx.y;          /* 0..10 */
    const int tid = ty*32 + tx;
    const int b    = blockIdx.x >> 1;
    const int half = blockIdx.x & 1;
    const int s0   = half * HALF_S;

    /* soft-pass thread mapping: lane -> (grp, o); c = ty*3 + grp */
    const int grp    = tx / 10;                 /* 0..3 (3 = leftover lanes) */
    const int os     = tx - grp*10;             /* o for soft passes */
    const int base   = grp*10;
    const int csf    = ty*3 + grp;
    const int active = (grp < 3) && (csf < CC);
    const int cs     = active ? csf : (CC-1);
    /* rotation shuffle sources for 10-lane max all-reduce */
    const int r1s = base + ((os+1)%10);
    const int r2s = base + ((os+2)%10);
    const int r4s = base + ((os+4)%10);
    const int r8s = base + ((os+8)%10);

    for (int i = tid; i < HALF_S*CC; i += TPB)
        sh.act[i] = act[(size_t)b*NN + (size_t)s0*CC + i];
    if (tid < HALF_S){
        const int s = s0 + tid;
        sh.offs[tid] = pk2(((s % WW) + 0.5f)*(1.0f/WW),
                           ((s / WW) + 0.5f)*(1.0f/HH));
    }
    if (tid == 0) sh.e0 = *(volatile unsigned*)&g_epoch;

    /* weights for the soft mapping (c=cs, o=os), replicated-packed */
    u64 wpk[4][4];
#pragma unroll
    for (int j = 0; j < 4; j++)
#pragma unroll
    for (int k = 0; k < 4; k++){
        const float wv = wmat[((size_t)(cs*OO + os))*16 + j*4 + k];
        wpk[j][k] = pk2(wv, wv);
    }
    __syncthreads();
    const unsigned e0 = sh.e0;

    const float* pose_blk = pose + ((size_t)b*NN + (size_t)s0*CC)*16;
    const size_t gpo = ((size_t)half*BB + b)*OO*33;        /* base for this block */
    float* gp_it0 = &g_part[0][gpo + (size_t)ty*33];       /* old-mapping per-o row */

    stats_zero_fact(pose_blk, &sh, wmat, tx, ty, gp_it0, blockIdx.x);
    grid_barrier(e0 + 1);
    block_finalize(0, b, tid, &sh, beta_a, beta_u, out);

    stats_pass_soft(pose_blk, &sh, wpk, tx, ty, os, base, active, cs,
                    r1s, r2s, r4s, r8s, &g_part[1][gpo]);
    grid_barrier(e0 + 2);
    block_finalize(1, b, tid, &sh, beta_a, beta_u, out);

    stats_pass_soft(pose_blk, &sh, wpk, tx, ty, os, base, active, cs,
                    r1s, r2s, r4s, r8s, &g_part[0][gpo]);
    grid_barrier(e0 + 3);
    if (half == 0)
        block_finalize(2, b, tid, &sh, beta_a, beta_u, out);
}

extern "C" void kernel_launch(void* const* d_in, const int* in_sizes, int n_in,
                              void* d_out, int out_size)
{
    const float* pose = (const float*)d_in[0];  // (B,H,W,C,16)
    const float* actv = (const float*)d_in[1];  // (B,H,W,C,1)
    const float* wmat = (const float*)d_in[2];  // (C,O,4,4)
    const float* ba   = (const float*)d_in[3];  // (1,1,O,1)
    const float* bu   = (const float*)d_in[4];  // (1,1,O,1)
    float* out = (float*)d_out;                 // pose(B,O,16) then act(B,O)

    dim3 blk(32, 11);
    fccaps_kernel<<<NBLK, blk>>>(pose, actv, wmat, ba, bu, out);
}